// round 8
// baseline (speedup 1.0000x reference)
#include <cuda_runtime.h>
#include <cuda_fp16.h>
#include <stdint.h>

#define N_MAX 100000
#define E_MAX 6400000
#define SCAN_T 1024

// ---- scratch (device globals: no allocation allowed) ----
__device__ int      g_ssrc[E_MAX];      // src indices sorted by dst (CSR adjacency)
__device__ unsigned g_deg[N_MAX];
__device__ int      g_off[N_MAX + 1];   // CSR row offsets
__device__ int      g_woff[N_MAX];      // working offsets for scatter
__device__ float    g_dinv[N_MAX];
__device__ __half   g_val[N_MAX];       // per-node payload (fp16, 195KB)
__device__ float    g_agg[N_MAX];       // layer-1 result s1 = dinv * sum
__device__ int      g_is64;

// ---------------------------------------------------------------------------
// threefry2x32 — exact JAX schedule: 20 rounds = 5 blocks of 4
// ---------------------------------------------------------------------------
__host__ __device__ __forceinline__ void tf2x32(uint32_t k0, uint32_t k1,
                                                uint32_t x0, uint32_t x1,
                                                uint32_t &o0, uint32_t &o1) {
    const uint32_t ks2 = k0 ^ k1 ^ 0x1BD11BDAu;
#define TF_RND(R) { x0 += x1; x1 = (x1 << (R)) | (x1 >> (32 - (R))); x1 ^= x0; }
    x0 += k0; x1 += k1;
    TF_RND(13) TF_RND(15) TF_RND(26) TF_RND(6)
    x0 += k1;  x1 += ks2 + 1u;
    TF_RND(17) TF_RND(29) TF_RND(16) TF_RND(24)
    x0 += ks2; x1 += k0 + 2u;
    TF_RND(13) TF_RND(15) TF_RND(26) TF_RND(6)
    x0 += k0;  x1 += k1 + 3u;
    TF_RND(17) TF_RND(29) TF_RND(16) TF_RND(24)
    x0 += k1;  x1 += ks2 + 4u;
    TF_RND(13) TF_RND(15) TF_RND(26) TF_RND(6)
    x0 += ks2; x1 += k0 + 5u;
#undef TF_RND
    o0 = x0; o1 = x1;
}

__device__ __forceinline__ bool keep_bit(uint32_t ka, uint32_t kb, uint32_t idx) {
    uint32_t a, b;
    tf2x32(ka, kb, 0u, idx, a, b);
    uint32_t bits = a ^ b;
    float u = __uint_as_float((bits >> 9) | 0x3f800000u) - 1.0f;
    return u < 0.4f;
}

// ---------------------------------------------------------------------------
// kernels
// ---------------------------------------------------------------------------

// zero deg + dtype detection
__global__ void k_init(const unsigned* __restrict__ e, int N) {
    int n = blockIdx.x * blockDim.x + threadIdx.x;
    if (n < N) g_deg[n] = 0u;
    if (blockIdx.x == 0) {
        __shared__ int any32;
        if (threadIdx.x == 0) any32 = 0;
        __syncthreads();
        int local = 0;
        for (int j = threadIdx.x; j < 4096; j += blockDim.x)
            if (e[2 * j + 1] != 0u) local = 1;
        if (local) any32 = 1;
        __syncthreads();
        if (threadIdx.x == 0) g_is64 = (any32 == 0) ? 1 : 0;
    }
}

// in-degree histogram over dst row; 4 edges/thread
__global__ void __launch_bounds__(256) k_deg(const long long* __restrict__ e, int E) {
    int i = blockIdx.x * blockDim.x + threadIdx.x;
    if (i * 4 >= E) return;
    int4 dv;
    if (g_is64) {
        const longlong2* d2 = reinterpret_cast<const longlong2*>(e + E);
        longlong2 da = d2[2 * i], db = d2[2 * i + 1];
        dv = make_int4((int)da.x, (int)da.y, (int)db.x, (int)db.y);
    } else {
        const int* e32 = reinterpret_cast<const int*>(e);
        dv = reinterpret_cast<const int4*>(e32 + E)[i];
    }
    atomicAdd(&g_deg[dv.x], 1u);
    atomicAdd(&g_deg[dv.y], 1u);
    atomicAdd(&g_deg[dv.z], 1u);
    atomicAdd(&g_deg[dv.w], 1u);
}

// single-block exclusive scan of deg -> off/woff, plus dinv
__global__ void __launch_bounds__(SCAN_T) k_scan(int N) {
    __shared__ int s_sum[SCAN_T];
    int t = threadIdx.x;
    int chunk = (N + SCAN_T - 1) / SCAN_T;
    int beg = t * chunk, end = min(beg + chunk, N);
    int local = 0;
    for (int n = beg; n < end; n++) local += (int)g_deg[n];
    s_sum[t] = local;
    __syncthreads();
    // Hillis-Steele inclusive scan on 1024 entries
    for (int o = 1; o < SCAN_T; o <<= 1) {
        int v = s_sum[t];
        int u = (t >= o) ? s_sum[t - o] : 0;
        __syncthreads();
        s_sum[t] = v + u;
        __syncthreads();
    }
    int run = (t == 0) ? 0 : s_sum[t - 1];   // exclusive base
    for (int n = beg; n < end; n++) {
        unsigned dg = g_deg[n];
        g_off[n] = run;
        g_woff[n] = run;
        g_dinv[n] = dg ? rsqrtf((float)dg) : 0.0f;
        run += (int)dg;
    }
    if (t == SCAN_T - 1) g_off[N] = run;
}

// counting-sort scatter: sorted-by-dst src list; 4 edges/thread
__global__ void __launch_bounds__(256) k_scatter(const long long* __restrict__ e, int E) {
    int i = blockIdx.x * blockDim.x + threadIdx.x;
    if (i * 4 >= E) return;
    int4 sv, dv;
    if (g_is64) {
        const longlong2* s2 = reinterpret_cast<const longlong2*>(e);
        const longlong2* d2 = reinterpret_cast<const longlong2*>(e + E);
        longlong2 sa = s2[2 * i], sb = s2[2 * i + 1];
        longlong2 da = d2[2 * i], db = d2[2 * i + 1];
        sv = make_int4((int)sa.x, (int)sa.y, (int)sb.x, (int)sb.y);
        dv = make_int4((int)da.x, (int)da.y, (int)db.x, (int)db.y);
    } else {
        const int* e32 = reinterpret_cast<const int*>(e);
        sv = reinterpret_cast<const int4*>(e32)[i];
        dv = reinterpret_cast<const int4*>(e32 + E)[i];
    }
    g_ssrc[atomicAdd(&g_woff[dv.x], 1)] = sv.x;
    g_ssrc[atomicAdd(&g_woff[dv.y], 1)] = sv.y;
    g_ssrc[atomicAdd(&g_woff[dv.z], 1)] = sv.z;
    g_ssrc[atomicAdd(&g_woff[dv.w], 1)] = sv.w;
}

// Per-node: dropout1 on x, val1 = h1 * dinv (fp16)
__global__ void k_node1(const float* __restrict__ x, int N, uint32_t ka, uint32_t kb) {
    int n = blockIdx.x * blockDim.x + threadIdx.x;
    if (n >= N) return;
    float h = keep_bit(ka, kb, (uint32_t)n) ? x[n] * 2.5f : 0.0f;
    g_val[n] = __float2half_rn(h * g_dinv[n]);
}

// CSR aggregation, warp per node, gather table staged in SMEM.
// dst_out[n] = dinv[n] * sum(val[ssrc[e]]) + bias
__global__ void __launch_bounds__(1024, 1) k_csr(float* __restrict__ dst_out,
                                                 const float* __restrict__ bias,
                                                 int has_bias, int N) {
    extern __shared__ __half s_val[];
    int n_u2 = (N + 3) / 4;   // uint2 = 4 halves
    const uint2* src_tbl = reinterpret_cast<const uint2*>(g_val);
    uint2* dst_tbl = reinterpret_cast<uint2*>(s_val);
    for (int j = threadIdx.x; j < n_u2; j += blockDim.x)
        dst_tbl[j] = src_tbl[j];
    __syncthreads();
    float b = has_bias ? __ldg(&bias[0]) : 0.0f;

    int lane = threadIdx.x & 31;
    int warp = (blockIdx.x * blockDim.x + threadIdx.x) >> 5;
    int nwarps = (gridDim.x * blockDim.x) >> 5;
    for (int n = warp; n < N; n += nwarps) {
        int beg = g_off[n], end = g_off[n + 1];
        float sum = 0.0f;
        for (int ei = beg + lane; ei < end; ei += 32)
            sum += __half2float(s_val[g_ssrc[ei]]);
#pragma unroll
        for (int o = 16; o; o >>= 1)
            sum += __shfl_down_sync(0xFFFFFFFFu, sum, o);
        if (lane == 0)
            dst_out[n] = sum * g_dinv[n] + b;
    }
}

// Per-node: s1 -> relu+dropout2 (16ch) -> dot W2 -> val2 = t*dinv (fp16)
__global__ void k_node2(const float* __restrict__ W1, const float* __restrict__ b1,
                        const float* __restrict__ W2, int N,
                        uint32_t ka, uint32_t kb) {
    int n = blockIdx.x * blockDim.x + threadIdx.x;
    if (n >= N) return;
    float s1 = g_agg[n];
    uint32_t base = (uint32_t)n * 16u;
    float t = 0.0f;
#pragma unroll
    for (int c = 0; c < 16; c++) {
        float v = fmaxf(fmaf(s1, __ldg(&W1[c]), __ldg(&b1[c])), 0.0f);
        if (keep_bit(ka, kb, base + (uint32_t)c))
            t = fmaf(v * 2.5f, __ldg(&W2[c]), t);
    }
    g_val[n] = __float2half_rn(t * g_dinv[n]);
}

// ---------------------------------------------------------------------------
// launch
// ---------------------------------------------------------------------------
extern "C" void kernel_launch(void* const* d_in, const int* in_sizes, int n_in,
                              void* d_out, int out_size) {
    const float*     x  = (const float*)d_in[0];
    const long long* ei = (const long long*)d_in[1];
    const float*     W1 = (const float*)d_in[2];
    const float*     b1 = (const float*)d_in[3];
    const float*     W2 = (const float*)d_in[4];
    const float*     b2 = (const float*)d_in[5];
    float* out = (float*)d_out;

    int N = in_sizes[0];
    int E = in_sizes[1] / 2;

    // JAX: key(42)=(0,42); partitionable split: subkey i = threefry(key,(0,i))
    uint32_t k1a, k1b, k2a, k2b;
    tf2x32(0u, 42u, 0u, 0u, k1a, k1b);
    tf2x32(0u, 42u, 0u, 1u, k2a, k2b);

    float* p_agg = nullptr;
    cudaGetSymbolAddress((void**)&p_agg, g_agg);

    size_t smem_bytes = (((size_t)N * sizeof(__half)) + 15) & ~(size_t)15;
    cudaFuncSetAttribute(k_csr, cudaFuncAttributeMaxDynamicSharedMemorySize,
                         (int)smem_bytes);

    const int T = 256;
    int nb = (N + T - 1) / T;
    int e4 = (E + 3) / 4;
    int eb = (e4 + T - 1) / T;

    k_init   <<<nb, T>>>((const unsigned*)ei, N);
    k_deg    <<<eb, T>>>(ei, E);
    k_scan   <<<1, SCAN_T>>>(N);
    k_scatter<<<eb, T>>>(ei, E);
    k_node1  <<<nb, T>>>(x, N, k1a, k1b);
    k_csr    <<<148, 1024, smem_bytes>>>(p_agg, nullptr, 0, N);
    k_node2  <<<nb, T>>>(W1, b1, W2, N, k2a, k2b);
    k_csr    <<<148, 1024, smem_bytes>>>(out, b2, 1, N);
}

// round 9
// speedup vs baseline: 2.6845x; 2.6845x over previous
#include <cuda_runtime.h>
#include <cuda_fp16.h>
#include <stdint.h>

#define N_MAX 100000
#define E_MAX 6400000

// ---- scratch (device globals: no allocation allowed) ----
__device__ int      g_src[E_MAX];
__device__ int      g_dst[E_MAX];
__device__ unsigned g_deg[N_MAX];
__device__ float    g_dinv[N_MAX];
__device__ __half   g_val[N_MAX];   // per-node payload (fp16, 195KB)
__device__ float    g_agg[N_MAX];   // layer-1 aggregation (fp32 atomics)
__device__ int      g_is64;         // edge_index dtype flag (1 = int64)

// ---------------------------------------------------------------------------
// threefry2x32 — exact JAX schedule: 20 rounds = 5 blocks of 4
// ---------------------------------------------------------------------------
__host__ __device__ __forceinline__ void tf2x32(uint32_t k0, uint32_t k1,
                                                uint32_t x0, uint32_t x1,
                                                uint32_t &o0, uint32_t &o1) {
    const uint32_t ks2 = k0 ^ k1 ^ 0x1BD11BDAu;
#define TF_RND(R) { x0 += x1; x1 = (x1 << (R)) | (x1 >> (32 - (R))); x1 ^= x0; }
    x0 += k0; x1 += k1;
    TF_RND(13) TF_RND(15) TF_RND(26) TF_RND(6)
    x0 += k1;  x1 += ks2 + 1u;
    TF_RND(17) TF_RND(29) TF_RND(16) TF_RND(24)
    x0 += ks2; x1 += k0 + 2u;
    TF_RND(13) TF_RND(15) TF_RND(26) TF_RND(6)
    x0 += k0;  x1 += k1 + 3u;
    TF_RND(17) TF_RND(29) TF_RND(16) TF_RND(24)
    x0 += k1;  x1 += ks2 + 4u;
    TF_RND(13) TF_RND(15) TF_RND(26) TF_RND(6)
    x0 += ks2; x1 += k0 + 5u;
#undef TF_RND
    o0 = x0; o1 = x1;
}

__device__ __forceinline__ bool keep_bit(uint32_t ka, uint32_t kb, uint32_t idx) {
    uint32_t a, b;
    tf2x32(ka, kb, 0u, idx, a, b);
    uint32_t bits = a ^ b;
    float u = __uint_as_float((bits >> 9) | 0x3f800000u) - 1.0f;
    return u < 0.4f;
}

// ---------------------------------------------------------------------------
// kernels
// ---------------------------------------------------------------------------

// zero counters/accumulators/out + dtype detection (block 0)
__global__ void k_init(float* __restrict__ out, const unsigned* __restrict__ e, int N) {
    int n = blockIdx.x * blockDim.x + threadIdx.x;
    if (n < N) { g_deg[n] = 0u; g_agg[n] = 0.0f; out[n] = 0.0f; }
    if (blockIdx.x == 0) {
        __shared__ int any32;
        if (threadIdx.x == 0) any32 = 0;
        __syncthreads();
        int local = 0;
        for (int j = threadIdx.x; j < 4096; j += blockDim.x)
            if (e[2 * j + 1] != 0u) local = 1;
        if (local) any32 = 1;
        __syncthreads();
        if (threadIdx.x == 0) g_is64 = (any32 == 0) ? 1 : 0;
    }
}

// Convert edge_index -> int32 src/dst and count in-degree. 4 edges per thread.
__global__ void __launch_bounds__(256) k_convert(const long long* __restrict__ e, int E) {
    int i = blockIdx.x * blockDim.x + threadIdx.x;   // quad index
    if (i * 4 >= E) return;
    int4 sv, dv;
    if (g_is64) {
        const longlong2* s2 = reinterpret_cast<const longlong2*>(e);
        const longlong2* d2 = reinterpret_cast<const longlong2*>(e + E);
        longlong2 sa = s2[2 * i], sb = s2[2 * i + 1];
        longlong2 da = d2[2 * i], db = d2[2 * i + 1];
        sv = make_int4((int)sa.x, (int)sa.y, (int)sb.x, (int)sb.y);
        dv = make_int4((int)da.x, (int)da.y, (int)db.x, (int)db.y);
    } else {
        const int* e32 = reinterpret_cast<const int*>(e);
        sv = reinterpret_cast<const int4*>(e32)[i];
        dv = reinterpret_cast<const int4*>(e32 + E)[i];
    }
    reinterpret_cast<int4*>(g_src)[i] = sv;
    reinterpret_cast<int4*>(g_dst)[i] = dv;
    atomicAdd(&g_deg[dv.x], 1u);
    atomicAdd(&g_deg[dv.y], 1u);
    atomicAdd(&g_deg[dv.z], 1u);
    atomicAdd(&g_deg[dv.w], 1u);
}

// Per-node: dinv, dropout1 on x, g1 = h1 * dinv  (stored fp16)
__global__ void k_node1(const float* __restrict__ x, int N, uint32_t ka, uint32_t kb) {
    int n = blockIdx.x * blockDim.x + threadIdx.x;
    if (n >= N) return;
    unsigned dg = g_deg[n];
    float dinv = dg ? rsqrtf((float)dg) : 0.0f;
    g_dinv[n] = dinv;
    float h = keep_bit(ka, kb, (uint32_t)n) ? x[n] * 2.5f : 0.0f;
    g_val[n] = __float2half_rn(h * dinv);
}

// Edge scatter: agg[dst] += val[src].
// fp16 node table staged in SMEM (random LDS gather ~0.15 cyc/edge);
// index loads software-pipelined so DRAM latency overlaps LDS+RED work.
__global__ void __launch_bounds__(1024, 1) k_edge(float* __restrict__ agg, int n4, int N) {
    extern __shared__ __half s_val[];
    int n_u4 = (N + 7) / 8;   // uint4 = 8 halves
    const uint4* st = reinterpret_cast<const uint4*>(g_val);
    uint4* dt = reinterpret_cast<uint4*>(s_val);
    for (int j = threadIdx.x; j < n_u4; j += blockDim.x)
        dt[j] = st[j];
    __syncthreads();

    const int4* s4 = reinterpret_cast<const int4*>(g_src);
    const int4* d4 = reinterpret_cast<const int4*>(g_dst);
    int stride = gridDim.x * blockDim.x;
    int i = blockIdx.x * blockDim.x + threadIdx.x;

    int4 s, d;
    bool valid = (i < n4);
    if (valid) { s = s4[i]; d = d4[i]; }
    while (valid) {
        int ni = i + stride;
        bool nvalid = (ni < n4);
        int4 ns, nd;
        if (nvalid) { ns = s4[ni]; nd = d4[ni]; }   // prefetch next iteration
        float v0 = __half2float(s_val[s.x]);
        float v1 = __half2float(s_val[s.y]);
        float v2 = __half2float(s_val[s.z]);
        float v3 = __half2float(s_val[s.w]);
        atomicAdd(&agg[d.x], v0);
        atomicAdd(&agg[d.y], v1);
        atomicAdd(&agg[d.z], v2);
        atomicAdd(&agg[d.w], v3);
        i = ni; s = ns; d = nd; valid = nvalid;
    }
}

// Per-node: s1 = agg*dinv ; relu + dropout2 (16 ch) ; dot W2 ; g2 = t*dinv (fp16)
__global__ void k_node2(const float* __restrict__ W1, const float* __restrict__ b1,
                        const float* __restrict__ W2, int N,
                        uint32_t ka, uint32_t kb) {
    int n = blockIdx.x * blockDim.x + threadIdx.x;
    if (n >= N) return;
    float dinv = g_dinv[n];
    float s1 = g_agg[n] * dinv;
    uint32_t base = (uint32_t)n * 16u;
    float t = 0.0f;
#pragma unroll
    for (int c = 0; c < 16; c++) {
        float v = fmaxf(fmaf(s1, __ldg(&W1[c]), __ldg(&b1[c])), 0.0f);
        if (keep_bit(ka, kb, base + (uint32_t)c))
            t = fmaf(v * 2.5f, __ldg(&W2[c]), t);
    }
    g_val[n] = __float2half_rn(t * dinv);
}

__global__ void k_final(float* __restrict__ out, const float* __restrict__ b2, int N) {
    int n = blockIdx.x * blockDim.x + threadIdx.x;
    if (n >= N) return;
    out[n] = out[n] * g_dinv[n] + __ldg(&b2[0]);
}

// ---------------------------------------------------------------------------
// launch
// ---------------------------------------------------------------------------
extern "C" void kernel_launch(void* const* d_in, const int* in_sizes, int n_in,
                              void* d_out, int out_size) {
    const float*     x  = (const float*)d_in[0];
    const long long* ei = (const long long*)d_in[1];
    const float*     W1 = (const float*)d_in[2];
    const float*     b1 = (const float*)d_in[3];
    const float*     W2 = (const float*)d_in[4];
    const float*     b2 = (const float*)d_in[5];
    float* out = (float*)d_out;

    int N = in_sizes[0];
    int E = in_sizes[1] / 2;

    // JAX: key(42)=(0,42); partitionable split: subkey i = threefry(key,(0,i))
    uint32_t k1a, k1b, k2a, k2b;
    tf2x32(0u, 42u, 0u, 0u, k1a, k1b);
    tf2x32(0u, 42u, 0u, 1u, k2a, k2b);

    float* p_agg = nullptr;
    cudaGetSymbolAddress((void**)&p_agg, g_agg);

    size_t smem_bytes = (((size_t)N * sizeof(__half)) + 15) & ~(size_t)15;
    cudaFuncSetAttribute(k_edge, cudaFuncAttributeMaxDynamicSharedMemorySize,
                         (int)smem_bytes);

    const int T = 256;
    int nb = (N + T - 1) / T;
    int e4 = (E + 3) / 4;
    int cb = (e4 + T - 1) / T;

    k_init   <<<nb, T>>>(out, (const unsigned*)ei, N);
    k_convert<<<cb, T>>>(ei, E);
    k_node1  <<<nb, T>>>(x, N, k1a, k1b);
    k_edge   <<<148, 1024, smem_bytes>>>(p_agg, e4, N);
    k_node2  <<<nb, T>>>(W1, b1, W2, N, k2a, k2b);
    k_edge   <<<148, 1024, smem_bytes>>>(out, e4, N);
    k_final  <<<nb, T>>>(out, b2, N);
}

// round 10
// speedup vs baseline: 3.1658x; 1.1793x over previous
#include <cuda_runtime.h>
#include <cuda_fp16.h>
#include <stdint.h>

#define N_MAX 100000
#define E_MAX 6400000

// ---- scratch (device globals: no allocation allowed) ----
__device__ int      g_src[E_MAX];
__device__ int      g_dst[E_MAX];
__device__ unsigned g_deg[N_MAX];
__device__ float    g_dinv[N_MAX];
__device__ __half   g_val[N_MAX];   // per-node payload (fp16, 195KB)
__device__ float    g_agg[N_MAX];   // layer-1 aggregation (fp32 atomics)
__device__ int      g_is64;         // edge_index dtype flag (1 = int64)

// ---------------------------------------------------------------------------
// threefry2x32 — exact JAX schedule: 20 rounds = 5 blocks of 4
// ---------------------------------------------------------------------------
__host__ __device__ __forceinline__ void tf2x32(uint32_t k0, uint32_t k1,
                                                uint32_t x0, uint32_t x1,
                                                uint32_t &o0, uint32_t &o1) {
    const uint32_t ks2 = k0 ^ k1 ^ 0x1BD11BDAu;
#define TF_RND(R) { x0 += x1; x1 = (x1 << (R)) | (x1 >> (32 - (R))); x1 ^= x0; }
    x0 += k0; x1 += k1;
    TF_RND(13) TF_RND(15) TF_RND(26) TF_RND(6)
    x0 += k1;  x1 += ks2 + 1u;
    TF_RND(17) TF_RND(29) TF_RND(16) TF_RND(24)
    x0 += ks2; x1 += k0 + 2u;
    TF_RND(13) TF_RND(15) TF_RND(26) TF_RND(6)
    x0 += k0;  x1 += k1 + 3u;
    TF_RND(17) TF_RND(29) TF_RND(16) TF_RND(24)
    x0 += k1;  x1 += ks2 + 4u;
    TF_RND(13) TF_RND(15) TF_RND(26) TF_RND(6)
    x0 += ks2; x1 += k0 + 5u;
#undef TF_RND
    o0 = x0; o1 = x1;
}

__device__ __forceinline__ bool keep_bit(uint32_t ka, uint32_t kb, uint32_t idx) {
    uint32_t a, b;
    tf2x32(ka, kb, 0u, idx, a, b);
    uint32_t bits = a ^ b;
    float u = __uint_as_float((bits >> 9) | 0x3f800000u) - 1.0f;
    return u < 0.4f;
}

// ---------------------------------------------------------------------------
// kernels
// ---------------------------------------------------------------------------

// zero counters/accumulators/out + dtype detection (block 0)
__global__ void k_init(float* __restrict__ out, const unsigned* __restrict__ e, int N) {
    int n = blockIdx.x * blockDim.x + threadIdx.x;
    if (n < N) { g_deg[n] = 0u; g_agg[n] = 0.0f; out[n] = 0.0f; }
    if (blockIdx.x == 0) {
        __shared__ int any32;
        if (threadIdx.x == 0) any32 = 0;
        __syncthreads();
        int local = 0;
        for (int j = threadIdx.x; j < 4096; j += blockDim.x)
            if (e[2 * j + 1] != 0u) local = 1;
        if (local) any32 = 1;
        __syncthreads();
        if (threadIdx.x == 0) g_is64 = (any32 == 0) ? 1 : 0;
    }
}

// Convert edge_index -> int32 src/dst and count in-degree. 4 edges per thread.
__global__ void __launch_bounds__(256) k_convert(const long long* __restrict__ e, int E) {
    int i = blockIdx.x * blockDim.x + threadIdx.x;   // quad index
    if (i * 4 >= E) return;
    int4 sv, dv;
    if (g_is64) {
        const longlong2* s2 = reinterpret_cast<const longlong2*>(e);
        const longlong2* d2 = reinterpret_cast<const longlong2*>(e + E);
        longlong2 sa = s2[2 * i], sb = s2[2 * i + 1];
        longlong2 da = d2[2 * i], db = d2[2 * i + 1];
        sv = make_int4((int)sa.x, (int)sa.y, (int)sb.x, (int)sb.y);
        dv = make_int4((int)da.x, (int)da.y, (int)db.x, (int)db.y);
    } else {
        const int* e32 = reinterpret_cast<const int*>(e);
        sv = reinterpret_cast<const int4*>(e32)[i];
        dv = reinterpret_cast<const int4*>(e32 + E)[i];
    }
    reinterpret_cast<int4*>(g_src)[i] = sv;
    reinterpret_cast<int4*>(g_dst)[i] = dv;
    atomicAdd(&g_deg[dv.x], 1u);
    atomicAdd(&g_deg[dv.y], 1u);
    atomicAdd(&g_deg[dv.z], 1u);
    atomicAdd(&g_deg[dv.w], 1u);
}

// Per-node: dinv, dropout1 on x, g1 = h1 * dinv  (stored fp16)
__global__ void k_node1(const float* __restrict__ x, int N, uint32_t ka, uint32_t kb) {
    int n = blockIdx.x * blockDim.x + threadIdx.x;
    if (n >= N) return;
    unsigned dg = g_deg[n];
    float dinv = dg ? rsqrtf((float)dg) : 0.0f;
    g_dinv[n] = dinv;
    float h = keep_bit(ka, kb, (uint32_t)n) ? x[n] * 2.5f : 0.0f;
    g_val[n] = __float2half_rn(h * dinv);
}

// Edge scatter: agg[dst] += val[src], SKIPPING zero contributions
// (dropout makes ~60% of pass-1 values exactly zero -> no atomic needed).
// fp16 node table staged in SMEM; index loads software-pipelined.
__global__ void __launch_bounds__(1024, 1) k_edge(float* __restrict__ agg, int n4, int N) {
    extern __shared__ __half s_val[];
    int n_u4 = (N + 7) / 8;   // uint4 = 8 halves
    const uint4* st = reinterpret_cast<const uint4*>(g_val);
    uint4* dt = reinterpret_cast<uint4*>(s_val);
    for (int j = threadIdx.x; j < n_u4; j += blockDim.x)
        dt[j] = st[j];
    __syncthreads();

    const int4* s4 = reinterpret_cast<const int4*>(g_src);
    const int4* d4 = reinterpret_cast<const int4*>(g_dst);
    int stride = gridDim.x * blockDim.x;
    int i = blockIdx.x * blockDim.x + threadIdx.x;

    int4 s, d;
    bool valid = (i < n4);
    if (valid) { s = s4[i]; d = d4[i]; }
    while (valid) {
        int ni = i + stride;
        bool nvalid = (ni < n4);
        int4 ns, nd;
        if (nvalid) { ns = s4[ni]; nd = d4[ni]; }   // prefetch next iteration
        float v0 = __half2float(s_val[s.x]);
        float v1 = __half2float(s_val[s.y]);
        float v2 = __half2float(s_val[s.z]);
        float v3 = __half2float(s_val[s.w]);
        if (v0 != 0.0f) atomicAdd(&agg[d.x], v0);
        if (v1 != 0.0f) atomicAdd(&agg[d.y], v1);
        if (v2 != 0.0f) atomicAdd(&agg[d.z], v2);
        if (v3 != 0.0f) atomicAdd(&agg[d.w], v3);
        i = ni; s = ns; d = nd; valid = nvalid;
    }
}

// Per-node: s1 = agg*dinv ; relu + dropout2 (16 ch) ; dot W2 ; g2 = t*dinv (fp16)
__global__ void k_node2(const float* __restrict__ W1, const float* __restrict__ b1,
                        const float* __restrict__ W2, int N,
                        uint32_t ka, uint32_t kb) {
    int n = blockIdx.x * blockDim.x + threadIdx.x;
    if (n >= N) return;
    float dinv = g_dinv[n];
    float s1 = g_agg[n] * dinv;
    uint32_t base = (uint32_t)n * 16u;
    float t = 0.0f;
#pragma unroll
    for (int c = 0; c < 16; c++) {
        float v = fmaxf(fmaf(s1, __ldg(&W1[c]), __ldg(&b1[c])), 0.0f);
        if (keep_bit(ka, kb, base + (uint32_t)c))
            t = fmaf(v * 2.5f, __ldg(&W2[c]), t);
    }
    g_val[n] = __float2half_rn(t * dinv);
}

__global__ void k_final(float* __restrict__ out, const float* __restrict__ b2, int N) {
    int n = blockIdx.x * blockDim.x + threadIdx.x;
    if (n >= N) return;
    out[n] = out[n] * g_dinv[n] + __ldg(&b2[0]);
}

// ---------------------------------------------------------------------------
// launch
// ---------------------------------------------------------------------------
extern "C" void kernel_launch(void* const* d_in, const int* in_sizes, int n_in,
                              void* d_out, int out_size) {
    const float*     x  = (const float*)d_in[0];
    const long long* ei = (const long long*)d_in[1];
    const float*     W1 = (const float*)d_in[2];
    const float*     b1 = (const float*)d_in[3];
    const float*     W2 = (const float*)d_in[4];
    const float*     b2 = (const float*)d_in[5];
    float* out = (float*)d_out;

    int N = in_sizes[0];
    int E = in_sizes[1] / 2;

    // JAX: key(42)=(0,42); partitionable split: subkey i = threefry(key,(0,i))
    uint32_t k1a, k1b, k2a, k2b;
    tf2x32(0u, 42u, 0u, 0u, k1a, k1b);
    tf2x32(0u, 42u, 0u, 1u, k2a, k2b);

    float* p_agg = nullptr;
    cudaGetSymbolAddress((void**)&p_agg, g_agg);

    size_t smem_bytes = (((size_t)N * sizeof(__half)) + 15) & ~(size_t)15;
    cudaFuncSetAttribute(k_edge, cudaFuncAttributeMaxDynamicSharedMemorySize,
                         (int)smem_bytes);

    const int T = 256;
    int nb = (N + T - 1) / T;
    int e4 = (E + 3) / 4;
    int cb = (e4 + T - 1) / T;

    k_init   <<<nb, T>>>(out, (const unsigned*)ei, N);
    k_convert<<<cb, T>>>(ei, E);
    k_node1  <<<nb, T>>>(x, N, k1a, k1b);
    k_edge   <<<148, 1024, smem_bytes>>>(p_agg, e4, N);
    k_node2  <<<nb, T>>>(W1, b1, W2, N, k2a, k2b);
    k_edge   <<<148, 1024, smem_bytes>>>(out, e4, N);
    k_final  <<<nb, T>>>(out, b2, N);
}